// round 14
// baseline (speedup 1.0000x reference)
#include <cuda_runtime.h>
#include <cuda_bf16.h>
#include <cuda_fp16.h>
#include <math.h>
#include <stdint.h>

// ---------------- problem constants ----------------
#define DIMN   1024
#define SEQ    2048
#define BATCH  2
#define TOK    (BATCH*SEQ)    // 4096 tokens
#define HEADS  16
#define HD     64
#define MLPD   4096
#define DEPTH  6
#define ASCALE 0.03125f       // DIM^-0.5 (reference uses full dim)

#define FLAG_RESID 1
#define FLAG_GELU  2
#define FLAG_PACK  4

// SW128 swizzle (Swizzle<3,4,3>) on byte offsets within a 128B-row tile
#define SWZ(o) ((o) ^ (((o) >> 3) & 0x70))

// ---------------- scratch (device globals; no cudaMalloc allowed) ----------------
// attention chain: single fp16 (tile = 128 rows x 64 k, SW128, 8192 elems = 16KB)
__device__ __half g_y16 [(size_t)TOK * DIMN];        // LN1 out
__device__ __half g_qp16[(size_t)TOK * 3 * DIMN];    // packed QKV
__device__ __half g_at16[(size_t)TOK * DIMN];        // attn out
// MLP chain: bf16 hi/lo
__device__ __nv_bfloat16 g_y_hi [(size_t)TOK * DIMN];
__device__ __nv_bfloat16 g_y_lo [(size_t)TOK * DIMN];
__device__ __nv_bfloat16 g_u_hi [(size_t)TOK * MLPD];
__device__ __nv_bfloat16 g_u_lo [(size_t)TOK * MLPD];
// weights (pre-transposed [N,K] K-major, pre-swizzled tiles)
__device__ __half g_wq16[(size_t)DEPTH * DIMN * 3 * DIMN];   // fp16 single
__device__ __half g_wo16[(size_t)DEPTH * DIMN * DIMN];       // fp16 single
__device__ __nv_bfloat16 g_w1_hi[(size_t)DEPTH * DIMN * MLPD];
__device__ __nv_bfloat16 g_w1_lo[(size_t)DEPTH * DIMN * MLPD];
__device__ __nv_bfloat16 g_w2_hi[(size_t)DEPTH * MLPD * DIMN];
__device__ __nv_bfloat16 g_w2_lo[(size_t)DEPTH * MLPD * DIMN];

// ---------------- helpers ----------------
__device__ __forceinline__ uint32_t smem_u32(const void* p) {
    uint32_t a;
    asm("{ .reg .u64 t; cvta.to.shared.u64 t, %1; cvt.u32.u64 %0, t; }"
        : "=r"(a) : "l"(p));
    return a;
}
__device__ __forceinline__ void cpasync16(uint32_t s, const void* g) {
    asm volatile("cp.async.cg.shared.global [%0], [%1], 16;" :: "r"(s), "l"(g));
}
#define CP_COMMIT() asm volatile("cp.async.commit_group;" ::: "memory")
#define CP_WAIT(n)  asm volatile("cp.async.wait_group %0;" :: "n"(n) : "memory")

#define LDM_X4(r, a)                                                          \
    asm volatile("ldmatrix.sync.aligned.m8n8.x4.shared.b16 {%0,%1,%2,%3}, [%4];" \
                 : "=r"((r)[0]), "=r"((r)[1]), "=r"((r)[2]), "=r"((r)[3])     \
                 : "r"(a))
#define LDM_X4T(r, a)                                                         \
    asm volatile("ldmatrix.sync.aligned.m8n8.x4.trans.shared.b16 {%0,%1,%2,%3}, [%4];" \
                 : "=r"((r)[0]), "=r"((r)[1]), "=r"((r)[2]), "=r"((r)[3])     \
                 : "r"(a))

__device__ __forceinline__ void mma_bf(float* c, const uint32_t* a,
                                       uint32_t b0, uint32_t b1) {
    asm volatile(
        "mma.sync.aligned.m16n8k16.row.col.f32.bf16.bf16.f32 "
        "{%0,%1,%2,%3}, {%4,%5,%6,%7}, {%8,%9}, {%0,%1,%2,%3};"
        : "+f"(c[0]), "+f"(c[1]), "+f"(c[2]), "+f"(c[3])
        : "r"(a[0]), "r"(a[1]), "r"(a[2]), "r"(a[3]), "r"(b0), "r"(b1));
}
__device__ __forceinline__ void mma_h(float* c, const uint32_t* a,
                                      uint32_t b0, uint32_t b1) {
    asm volatile(
        "mma.sync.aligned.m16n8k16.row.col.f32.f16.f16.f32 "
        "{%0,%1,%2,%3}, {%4,%5,%6,%7}, {%8,%9}, {%0,%1,%2,%3};"
        : "+f"(c[0]), "+f"(c[1]), "+f"(c[2]), "+f"(c[3])
        : "r"(a[0]), "r"(a[1]), "r"(a[2]), "r"(a[3]), "r"(b0), "r"(b1));
}

__device__ __forceinline__ float gelu_exact(float x) {
    return 0.5f * x * (1.0f + erff(x * 0.70710678118654752f));
}
// bf16 hi/lo pack
__device__ __forceinline__ void pack2(float a, float b, uint32_t& h, uint32_t& l) {
    const __nv_bfloat16 ha = __float2bfloat16(a);
    const __nv_bfloat16 hb = __float2bfloat16(b);
    const __nv_bfloat16 la = __float2bfloat16(a - __bfloat162float(ha));
    const __nv_bfloat16 lb = __float2bfloat16(b - __bfloat162float(hb));
    h = (uint32_t)__bfloat16_as_ushort(ha) | ((uint32_t)__bfloat16_as_ushort(hb) << 16);
    l = (uint32_t)__bfloat16_as_ushort(la) | ((uint32_t)__bfloat16_as_ushort(lb) << 16);
}
__device__ __forceinline__ uint32_t hpair(float a, float b) {
    return (uint32_t)__half_as_ushort(__float2half_rn(a)) |
           ((uint32_t)__half_as_ushort(__float2half_rn(b)) << 16);
}

// ---------------- layernorm core ----------------
__device__ __forceinline__ void ln_core(const float* x, const float* g,
                                        const float* b, int row, int tid,
                                        float* o, float* redS, float* redQ)
{
    const float4 v = reinterpret_cast<const float4*>(x)[(size_t)row * 256 + tid];
    float s = v.x + v.y + v.z + v.w;
    float q = v.x*v.x + v.y*v.y + v.z*v.z + v.w*v.w;
    #pragma unroll
    for (int off = 16; off; off >>= 1) {
        s += __shfl_xor_sync(0xffffffffu, s, off);
        q += __shfl_xor_sync(0xffffffffu, q, off);
    }
    if ((tid & 31) == 0) { redS[tid >> 5] = s; redQ[tid >> 5] = q; }
    __syncthreads();
    s = 0.f; q = 0.f;
    #pragma unroll
    for (int w = 0; w < 8; w++) { s += redS[w]; q += redQ[w]; }
    const float mean = s * (1.0f / DIMN);
    const float var  = q * (1.0f / DIMN) - mean * mean;
    const float rstd = rsqrtf(var + 1e-5f);
    const float4 gg = reinterpret_cast<const float4*>(g)[tid];
    const float4 bb = reinterpret_cast<const float4*>(b)[tid];
    o[0] = (v.x - mean) * rstd * gg.x + bb.x;
    o[1] = (v.y - mean) * rstd * gg.y + bb.y;
    o[2] = (v.z - mean) * rstd * gg.z + bb.z;
    o[3] = (v.w - mean) * rstd * gg.w + bb.w;
}

// LN -> bf16 hi/lo tiles (MLP path)
__global__ __launch_bounds__(256) void ln_pack_bf(
    const float* __restrict__ x, const float* __restrict__ g,
    const float* __restrict__ b, __nv_bfloat16* __restrict__ hi,
    __nv_bfloat16* __restrict__ lo)
{
    __shared__ float redS[8], redQ[8];
    const int row = blockIdx.x, tid = threadIdx.x;
    float o[4];
    ln_core(x, g, b, row, tid, o, redS, redQ);
    uint32_t h0, l0, h1, l1;
    pack2(o[0], o[1], h0, l0);
    pack2(o[2], o[3], h1, l1);
    const int k = tid << 2;
    const size_t tile = (size_t)(row >> 7) * (DIMN / 64) + (k >> 6);
    const uint32_t off = SWZ((uint32_t)((row & 127) * 128 + ((k & 63) << 1)));
    *reinterpret_cast<uint2*>((char*)hi + tile * 16384 + off) = make_uint2(h0, h1);
    *reinterpret_cast<uint2*>((char*)lo + tile * 16384 + off) = make_uint2(l0, l1);
}

// LN -> single fp16 tiles (attention path)
__global__ __launch_bounds__(256) void ln_pack_h(
    const float* __restrict__ x, const float* __restrict__ g,
    const float* __restrict__ b, __half* __restrict__ hi)
{
    __shared__ float redS[8], redQ[8];
    const int row = blockIdx.x, tid = threadIdx.x;
    float o[4];
    ln_core(x, g, b, row, tid, o, redS, redQ);
    const uint32_t h0 = hpair(o[0], o[1]);
    const uint32_t h1 = hpair(o[2], o[3]);
    const int k = tid << 2;
    const size_t tile = (size_t)(row >> 7) * (DIMN / 64) + (k >> 6);
    const uint32_t off = SWZ((uint32_t)((row & 127) * 128 + ((k & 63) << 1)));
    *reinterpret_cast<uint2*>((char*)hi + tile * 16384 + off) = make_uint2(h0, h1);
}

// ---------------- weight prep: fp32 W[K,N] -> bf16 hi/lo tiles ----------------
__global__ __launch_bounds__(256) void prep_bf(
    const float* __restrict__ W, __nv_bfloat16* __restrict__ hi,
    __nv_bfloat16* __restrict__ lo, int K, int N)
{
    __shared__ uint32_t shH[4096], shL[4096];
    const int nt = blockIdx.x, kc = blockIdx.y, layer = blockIdx.z;
    const float* Wp = W + (size_t)layer * K * N;
    const int tid = threadIdx.x;
    #pragma unroll
    for (int i = 0; i < 16; i++) {
        const int idx = tid + (i << 8);
        const int n  = idx & 127;
        const int r2 = idx >> 7;
        const size_t gbase = (size_t)(kc * 64 + 2 * r2) * N + nt * 128 + n;
        const float f0 = Wp[gbase];
        const float f1 = Wp[gbase + N];
        uint32_t h, l;
        pack2(f0, f1, h, l);
        const uint32_t w = SWZ((uint32_t)(n * 128 + (r2 << 2))) >> 2;
        shH[w] = h;
        shL[w] = l;
    }
    __syncthreads();
    const size_t tb = ((size_t)layer * gridDim.x * gridDim.y +
                       (size_t)nt * gridDim.y + kc) * 8192;
    uint4* dH = reinterpret_cast<uint4*>(hi + tb);
    uint4* dL = reinterpret_cast<uint4*>(lo + tb);
    const uint4* sH = reinterpret_cast<const uint4*>(shH);
    const uint4* sL = reinterpret_cast<const uint4*>(shL);
    #pragma unroll
    for (int i = 0; i < 4; i++) {
        const int idx = tid + (i << 8);
        dH[idx] = sH[idx];
        dL[idx] = sL[idx];
    }
}

// weight prep: fp32 W[K,N] -> single fp16 tiles
__global__ __launch_bounds__(256) void prep_h(
    const float* __restrict__ W, __half* __restrict__ hi, int K, int N)
{
    __shared__ uint32_t shH[4096];
    const int nt = blockIdx.x, kc = blockIdx.y, layer = blockIdx.z;
    const float* Wp = W + (size_t)layer * K * N;
    const int tid = threadIdx.x;
    #pragma unroll
    for (int i = 0; i < 16; i++) {
        const int idx = tid + (i << 8);
        const int n  = idx & 127;
        const int r2 = idx >> 7;
        const size_t gbase = (size_t)(kc * 64 + 2 * r2) * N + nt * 128 + n;
        const float f0 = Wp[gbase];
        const float f1 = Wp[gbase + N];
        const uint32_t w = SWZ((uint32_t)(n * 128 + (r2 << 2))) >> 2;
        shH[w] = hpair(f0, f1);
    }
    __syncthreads();
    const size_t tb = ((size_t)layer * gridDim.x * gridDim.y +
                       (size_t)nt * gridDim.y + kc) * 8192;
    uint4* dH = reinterpret_cast<uint4*>(hi + tb);
    const uint4* sH = reinterpret_cast<const uint4*>(shH);
    #pragma unroll
    for (int i = 0; i < 4; i++) {
        const int idx = tid + (i << 8);
        dH[idx] = sH[idx];
    }
}

// ---------------- mma.sync GEMM (TERMS=1 fp16 | TERMS=3 bf16) ----------------
// C[M,N] = A@W (+bias)(+gelu)(+resid | ->pack). 128x128 CTA tile, K-chunk 64,
// 3-stage cp.async pipeline, 8 warps each 32(m)x64(n).
#define STAGES 3
#define STG_BYTES 65536          // Ahi 16K | Alo 16K | Bhi 16K | Blo 16K
#define GEMM_SMEM (STAGES * STG_BYTES)

template<int TERMS, int HALF>
__global__ __launch_bounds__(256, 1) void gemm_mma(
    int M, int N, int K,
    const void* __restrict__ Ahi, const void* __restrict__ Alo,
    const void* __restrict__ Bhi, const void* __restrict__ Blo,
    float* __restrict__ C, const float* __restrict__ bias,
    void* __restrict__ Phi, void* __restrict__ Plo,
    int packNC, int loCols, int flags)
{
    extern __shared__ __align__(1024) char smem[];
    const uint32_t sb = smem_u32(smem);
    const int tid = threadIdx.x;
    const int wid = tid >> 5, lane = tid & 31;
    const int NC = K >> 6;
    const int bm = blockIdx.y << 7, bn = blockIdx.x << 7;
    const size_t at0 = (size_t)blockIdx.y * NC;
    const size_t bt0 = (size_t)blockIdx.x * NC;

    #pragma unroll
    for (int s = 0; s < STAGES; s++) {
        const char* ga_h = (const char*)Ahi + (at0 + s) * 16384;
        const char* gb_h = (const char*)Bhi + (bt0 + s) * 16384;
        const char* ga_l = (TERMS == 3) ? (const char*)Alo + (at0 + s) * 16384 : nullptr;
        const char* gb_l = (TERMS == 3) ? (const char*)Blo + (bt0 + s) * 16384 : nullptr;
        const uint32_t ds = sb + s * STG_BYTES;
        #pragma unroll
        for (int i = 0; i < 4; i++) {
            const int idx = (tid + (i << 8)) << 4;
            cpasync16(ds +     0 + idx, ga_h + idx);
            cpasync16(ds + 32768 + idx, gb_h + idx);
            if (TERMS == 3) {
                cpasync16(ds + 16384 + idx, ga_l + idx);
                cpasync16(ds + 49152 + idx, gb_l + idx);
            }
        }
        CP_COMMIT();
    }

    float acc[2][8][4];
    #pragma unroll
    for (int i = 0; i < 2; i++)
        #pragma unroll
        for (int j = 0; j < 8; j++)
            #pragma unroll
            for (int u = 0; u < 4; u++) acc[i][j][u] = 0.f;

    const int wm0 = (wid & 3) << 5;
    const int wn0 = (wid >> 2) << 6;
    uint32_t aoff[2], boff[4];
    #pragma unroll
    for (int mt = 0; mt < 2; mt++)
        aoff[mt] = (uint32_t)((wm0 + (mt << 4) + (lane & 15)) * 128 + ((lane >> 4) << 4));
    #pragma unroll
    for (int g = 0; g < 4; g++)
        boff[g] = (uint32_t)((wn0 + (g << 4) + (lane & 7) + ((lane >> 1) & 8)) * 128 +
                             ((lane & 8) << 1));

    for (int c = 0; c < NC; c++) {
        const int n_after = (c + STAGES <= NC ? STAGES : NC - c) - 1;
        if (n_after >= 2) CP_WAIT(2);
        else if (n_after == 1) CP_WAIT(1);
        else CP_WAIT(0);
        __syncthreads();

        const uint32_t stb = sb + (uint32_t)(c % STAGES) * STG_BYTES;
        #pragma unroll
        for (int ks = 0; ks < 4; ks++) {
            const uint32_t kb = (uint32_t)(ks << 5);
            uint32_t ah[2][4], bf4[4][4];
            #pragma unroll
            for (int mt = 0; mt < 2; mt++)
                LDM_X4(ah[mt], stb + SWZ(aoff[mt] + kb));
            #pragma unroll
            for (int g = 0; g < 4; g++)
                LDM_X4(bf4[g], stb + 32768 + SWZ(boff[g] + kb));
            #pragma unroll
            for (int mt = 0; mt < 2; mt++)
                #pragma unroll
                for (int g = 0; g < 4; g++) {
                    if (HALF) {
                        mma_h(acc[mt][2*g],   ah[mt], bf4[g][0], bf4[g][1]);
                        mma_h(acc[mt][2*g+1], ah[mt], bf4[g][2], bf4[g][3]);
                    } else {
                        mma_bf(acc[mt][2*g],   ah[mt], bf4[g][0], bf4[g][1]);
                        mma_bf(acc[mt][2*g+1], ah[mt], bf4[g][2], bf4[g][3]);
                    }
                }
            if (TERMS == 3) {
                uint32_t al[2][4];
                #pragma unroll
                for (int mt = 0; mt < 2; mt++)
                    LDM_X4(al[mt], stb + 16384 + SWZ(aoff[mt] + kb));
                #pragma unroll
                for (int mt = 0; mt < 2; mt++)
                    #pragma unroll
                    for (int g = 0; g < 4; g++) {
                        mma_bf(acc[mt][2*g],   al[mt], bf4[g][0], bf4[g][1]);
                        mma_bf(acc[mt][2*g+1], al[mt], bf4[g][2], bf4[g][3]);
                    }
                uint32_t bl4[4][4];
                #pragma unroll
                for (int g = 0; g < 4; g++)
                    LDM_X4(bl4[g], stb + 49152 + SWZ(boff[g] + kb));
                #pragma unroll
                for (int mt = 0; mt < 2; mt++)
                    #pragma unroll
                    for (int g = 0; g < 4; g++) {
                        mma_bf(acc[mt][2*g],   ah[mt], bl4[g][0], bl4[g][1]);
                        mma_bf(acc[mt][2*g+1], ah[mt], bl4[g][2], bl4[g][3]);
                    }
            }
        }
        __syncthreads();

        const int cn = c + STAGES;
        if (cn < NC) {
            const char* ga_h = (const char*)Ahi + (at0 + cn) * 16384;
            const char* gb_h = (const char*)Bhi + (bt0 + cn) * 16384;
            const char* ga_l = (TERMS == 3) ? (const char*)Alo + (at0 + cn) * 16384 : nullptr;
            const char* gb_l = (TERMS == 3) ? (const char*)Blo + (bt0 + cn) * 16384 : nullptr;
            const uint32_t ds = sb + (uint32_t)(c % STAGES) * STG_BYTES;
            #pragma unroll
            for (int i = 0; i < 4; i++) {
                const int idx = (tid + (i << 8)) << 4;
                cpasync16(ds +     0 + idx, ga_h + idx);
                cpasync16(ds + 32768 + idx, gb_h + idx);
                if (TERMS == 3) {
                    cpasync16(ds + 16384 + idx, ga_l + idx);
                    cpasync16(ds + 49152 + idx, gb_l + idx);
                }
            }
        }
        CP_COMMIT();
    }

    // ---- epilogue ----
    #pragma unroll
    for (int mt = 0; mt < 2; mt++) {
        const int r0 = bm + wm0 + (mt << 4) + (lane >> 2);
        #pragma unroll
        for (int nt = 0; nt < 8; nt++) {
            const int col = bn + wn0 + (nt << 3) + ((lane & 3) << 1);
            float va0 = acc[mt][nt][0], va1 = acc[mt][nt][1];
            float vb0 = acc[mt][nt][2], vb1 = acc[mt][nt][3];
            if (bias) {
                const float2 bv = *reinterpret_cast<const float2*>(bias + col);
                va0 += bv.x; va1 += bv.y; vb0 += bv.x; vb1 += bv.y;
            }
            if (flags & FLAG_GELU) {
                va0 = gelu_exact(va0); va1 = gelu_exact(va1);
                vb0 = gelu_exact(vb0); vb1 = gelu_exact(vb1);
            }
            if (flags & FLAG_PACK) {
                #pragma unroll
                for (int rr = 0; rr < 2; rr++) {
                    const int r = r0 + (rr << 3);
                    const float pa = rr ? vb0 : va0;
                    const float pb = rr ? vb1 : va1;
                    const size_t tile = (size_t)(r >> 7) * packNC + (col >> 6);
                    const uint32_t off = SWZ((uint32_t)((r & 127) * 128 + ((col & 63) << 1)));
                    if (HALF) {
                        *reinterpret_cast<uint32_t*>((char*)Phi + tile * 16384 + off) = hpair(pa, pb);
                    } else {
                        uint32_t hv, lv;
                        pack2(pa, pb, hv, lv);
                        *reinterpret_cast<uint32_t*>((char*)Phi + tile * 16384 + off) = hv;
                        if (col < loCols)
                            *reinterpret_cast<uint32_t*>((char*)Plo + tile * 16384 + off) = lv;
                    }
                }
            } else {
                float* p0 = C + (size_t)r0 * N + col;
                float* p1 = C + (size_t)(r0 + 8) * N + col;
                if (flags & FLAG_RESID) {
                    const float2 c0 = *reinterpret_cast<const float2*>(p0);
                    const float2 c1 = *reinterpret_cast<const float2*>(p1);
                    va0 += c0.x; va1 += c0.y; vb0 += c1.x; vb1 += c1.y;
                }
                *reinterpret_cast<float2*>(p0) = make_float2(va0, va1);
                *reinterpret_cast<float2*>(p1) = make_float2(vb0, vb1);
            }
        }
    }
}

// ---------------- mma.sync flash attention, single fp16, hd=64 ---------------
// CTA: 128 threads (4 warps), 64 q-rows, kv tiles of 64, double-buffered K/V.
#define ATT_SMEM (8192 + 2 * 16384)   // Q + 2 stages * (K 8K | V 8K)

__global__ __launch_bounds__(128, 3) void attn_mma(
    const __half* __restrict__ qkvh, __half* __restrict__ ohi)
{
    extern __shared__ __align__(1024) char asmem[];
    const uint32_t sb = smem_u32(asmem);
    const int tid = threadIdx.x;
    const int wid = tid >> 5, lane = tid & 31;
    const int bh = blockIdx.y;
    const int bb = bh >> 4, h = bh & 15;
    const int q0 = blockIdx.x << 6;
    const int grow0 = bb * SEQ + q0;
    const int hq = h;
    const int hk = (DIMN >> 6) + h;
    const int hv = (2 * DIMN >> 6) + h;

    auto src64 = [&](int coltile, int grows) -> const char* {
        return (const char*)qkvh + ((size_t)(grows >> 7) * 48 + coltile) * 16384
               + (size_t)(grows & 127) * 128;
    };
    auto issue_stage = [&](int it) {
        const int gkv = bb * SEQ + (it << 6);
        const char* kh_ = src64(hk, gkv);
        const char* vh_ = src64(hv, gkv);
        const uint32_t ds = sb + 8192 + (uint32_t)(it & 1) * 16384;
        #pragma unroll
        for (int i = 0; i < 4; i++) {
            const int idx = (tid + (i << 7)) << 4;
            cpasync16(ds +        idx, kh_ + idx);
            cpasync16(ds + 8192 + idx, vh_ + idx);
        }
    };

    // ---- prologue: Q + KV stage 0 ----
    {
        const char* qh_ = src64(hq, grow0);
        #pragma unroll
        for (int i = 0; i < 4; i++) {
            const int idx = (tid + (i << 7)) << 4;
            cpasync16(sb + idx, qh_ + idx);
        }
        issue_stage(0);
        CP_COMMIT();
    }
    CP_WAIT(0);
    __syncthreads();

    // ---- preload Q fragments ----
    const uint32_t aoff = (uint32_t)(((wid << 4) + (lane & 15)) * 128 + ((lane >> 4) << 4));
    uint32_t qhf[4][4];
    #pragma unroll
    for (int kb = 0; kb < 4; kb++)
        LDM_X4(qhf[kb], sb + SWZ(aoff + (kb << 5)));

    uint32_t boffK[4], voffV[4];
    #pragma unroll
    for (int g = 0; g < 4; g++) {
        boffK[g] = (uint32_t)(((g << 4) + (lane & 7) + ((lane >> 1) & 8)) * 128 +
                              ((lane & 8) << 1));
        voffV[g] = (uint32_t)((lane & 15) * 128 + ((lane >> 4) << 4) + (g << 5));
    }

    float oacc[8][4];
    #pragma unroll
    for (int j = 0; j < 8; j++)
        #pragma unroll
        for (int u = 0; u < 4; u++) oacc[j][u] = 0.f;
    float m0 = -1e30f, m1 = -1e30f, l0 = 0.f, l1 = 0.f;

    const int NIT = SEQ / 64;
    for (int it = 0; it < NIT; it++) {
        if (it + 1 < NIT) issue_stage(it + 1);
        CP_COMMIT();

        const uint32_t kbuf = sb + 8192 + (uint32_t)(it & 1) * 16384;
        const uint32_t vbuf = kbuf + 8192;

        // ---- S = Q K^T (single fp16) ----
        float sacc[8][4];
        #pragma unroll
        for (int j = 0; j < 8; j++)
            #pragma unroll
            for (int u = 0; u < 4; u++) sacc[j][u] = 0.f;

        #pragma unroll
        for (int kb = 0; kb < 4; kb++) {
            const uint32_t kbb = (uint32_t)(kb << 5);
            uint32_t bh4[4][4];
            #pragma unroll
            for (int g = 0; g < 4; g++)
                LDM_X4(bh4[g], kbuf + SWZ(boffK[g] + kbb));
            #pragma unroll
            for (int g = 0; g < 4; g++) {
                mma_h(sacc[2*g],   qhf[kb], bh4[g][0], bh4[g][1]);
                mma_h(sacc[2*g+1], qhf[kb], bh4[g][2], bh4[g][3]);
            }
        }

        // ---- online softmax ----
        #pragma unroll
        for (int j = 0; j < 8; j++)
            #pragma unroll
            for (int u = 0; u < 4; u++) sacc[j][u] *= ASCALE;

        float mx0 = -1e30f, mx1 = -1e30f;
        #pragma unroll
        for (int j = 0; j < 8; j++) {
            mx0 = fmaxf(mx0, fmaxf(sacc[j][0], sacc[j][1]));
            mx1 = fmaxf(mx1, fmaxf(sacc[j][2], sacc[j][3]));
        }
        mx0 = fmaxf(mx0, __shfl_xor_sync(0xffffffffu, mx0, 1));
        mx0 = fmaxf(mx0, __shfl_xor_sync(0xffffffffu, mx0, 2));
        mx1 = fmaxf(mx1, __shfl_xor_sync(0xffffffffu, mx1, 1));
        mx1 = fmaxf(mx1, __shfl_xor_sync(0xffffffffu, mx1, 2));
        const float nm0 = fmaxf(m0, mx0), nm1 = fmaxf(m1, mx1);
        const float al0 = __expf(m0 - nm0), al1 = __expf(m1 - nm1);
        m0 = nm0; m1 = nm1;
        float rs0 = 0.f, rs1 = 0.f;
        #pragma unroll
        for (int j = 0; j < 8; j++) {
            sacc[j][0] = __expf(sacc[j][0] - m0); rs0 += sacc[j][0];
            sacc[j][1] = __expf(sacc[j][1] - m0); rs0 += sacc[j][1];
            sacc[j][2] = __expf(sacc[j][2] - m1); rs1 += sacc[j][2];
            sacc[j][3] = __expf(sacc[j][3] - m1); rs1 += sacc[j][3];
        }
        l0 = l0 * al0 + rs0;
        l1 = l1 * al1 + rs1;
        #pragma unroll
        for (int j = 0; j < 8; j++) {
            oacc[j][0] *= al0; oacc[j][1] *= al0;
            oacc[j][2] *= al1; oacc[j][3] *= al1;
        }

        // ---- O += P V (single fp16 P and V) ----
        #pragma unroll
        for (int jp = 0; jp < 4; jp++) {
            uint32_t pah[4];
            pah[0] = hpair(sacc[2*jp][0],   sacc[2*jp][1]);
            pah[1] = hpair(sacc[2*jp][2],   sacc[2*jp][3]);
            pah[2] = hpair(sacc[2*jp+1][0], sacc[2*jp+1][1]);
            pah[3] = hpair(sacc[2*jp+1][2], sacc[2*jp+1][3]);
            const uint32_t rowb = (uint32_t)(jp << 11);     // 16 rows * 128B
            #pragma unroll
            for (int g = 0; g < 4; g++) {
                uint32_t vh4[4];
                LDM_X4T(vh4, vbuf + SWZ(voffV[g] + rowb));
                mma_h(oacc[2*g],   pah, vh4[0], vh4[1]);
                mma_h(oacc[2*g+1], pah, vh4[2], vh4[3]);
            }
        }

        if (it + 1 < NIT) CP_WAIT(0);
        __syncthreads();
    }

    // ---- finalize & write fp16 ----
    l0 += __shfl_xor_sync(0xffffffffu, l0, 1);
    l0 += __shfl_xor_sync(0xffffffffu, l0, 2);
    l1 += __shfl_xor_sync(0xffffffffu, l1, 1);
    l1 += __shfl_xor_sync(0xffffffffu, l1, 2);
    const float il0 = 1.0f / l0, il1 = 1.0f / l1;

    const int r0g = grow0 + (wid << 4) + (lane >> 2);
    #pragma unroll
    for (int j = 0; j < 8; j++) {
        const int k0 = h * HD + (j << 3) + ((lane & 3) << 1);
        const uint32_t hv0 = hpair(oacc[j][0] * il0, oacc[j][1] * il0);
        const uint32_t hv1 = hpair(oacc[j][2] * il1, oacc[j][3] * il1);
        const size_t t0 = (size_t)(r0g >> 7) * 16 + (k0 >> 6);
        const uint32_t of0 = SWZ((uint32_t)((r0g & 127) * 128 + ((k0 & 63) << 1)));
        *reinterpret_cast<uint32_t*>((char*)ohi + t0 * 16384 + of0) = hv0;
        const int r1g = r0g + 8;
        const size_t t1 = (size_t)(r1g >> 7) * 16 + (k0 >> 6);
        const uint32_t of1 = SWZ((uint32_t)((r1g & 127) * 128 + ((k0 & 63) << 1)));
        *reinterpret_cast<uint32_t*>((char*)ohi + t1 * 16384 + of1) = hv1;
    }
}

// ---------------- launch ----------------
extern "C" void kernel_launch(void* const* d_in, const int* in_sizes, int n_in,
                              void* d_out, int out_size)
{
    const float* x    = (const float*)d_in[0];
    const float* Wqkv = (const float*)d_in[1];
    const float* Wout = (const float*)d_in[2];
    const float* bout = (const float*)d_in[3];
    const float* ln1g = (const float*)d_in[4];
    const float* ln1b = (const float*)d_in[5];
    const float* ln2g = (const float*)d_in[6];
    const float* ln2b = (const float*)d_in[7];
    const float* W1   = (const float*)d_in[8];
    const float* b1   = (const float*)d_in[9];
    const float* W2   = (const float*)d_in[10];
    const float* b2   = (const float*)d_in[11];
    float* h = (float*)d_out;

    __half *y16, *qp16, *at16, *wq16, *wo16;
    cudaGetSymbolAddress((void**)&y16,  g_y16);
    cudaGetSymbolAddress((void**)&qp16, g_qp16);
    cudaGetSymbolAddress((void**)&at16, g_at16);
    cudaGetSymbolAddress((void**)&wq16, g_wq16);
    cudaGetSymbolAddress((void**)&wo16, g_wo16);
    __nv_bfloat16 *yh, *yl, *uh, *ul, *w1h, *w1l, *w2h, *w2l;
    cudaGetSymbolAddress((void**)&yh,  g_y_hi);
    cudaGetSymbolAddress((void**)&yl,  g_y_lo);
    cudaGetSymbolAddress((void**)&uh,  g_u_hi);
    cudaGetSymbolAddress((void**)&ul,  g_u_lo);
    cudaGetSymbolAddress((void**)&w1h, g_w1_hi);
    cudaGetSymbolAddress((void**)&w1l, g_w1_lo);
    cudaGetSymbolAddress((void**)&w2h, g_w2_hi);
    cudaGetSymbolAddress((void**)&w2l, g_w2_lo);

    cudaFuncSetAttribute(gemm_mma<1,1>, cudaFuncAttributeMaxDynamicSharedMemorySize, GEMM_SMEM);
    cudaFuncSetAttribute(gemm_mma<3,0>, cudaFuncAttributeMaxDynamicSharedMemorySize, GEMM_SMEM);
    cudaFuncSetAttribute(attn_mma, cudaFuncAttributeMaxDynamicSharedMemorySize, ATT_SMEM);

    // pack weights: fp16 single for Wqkv/Wout, bf16 hi+lo for W1/W2
    prep_h <<<dim3(3 * DIMN / 128, DIMN / 64, DEPTH), 256>>>(Wqkv, wq16, DIMN, 3 * DIMN);
    prep_h <<<dim3(DIMN / 128,     DIMN / 64, DEPTH), 256>>>(Wout, wo16, DIMN, DIMN);
    prep_bf<<<dim3(MLPD / 128,     DIMN / 64, DEPTH), 256>>>(W1, w1h, w1l, DIMN, MLPD);
    prep_bf<<<dim3(DIMN / 128,     MLPD / 64, DEPTH), 256>>>(W2, w2h, w2l, MLPD, DIMN);

    cudaMemcpyAsync(h, x, (size_t)TOK * DIMN * sizeof(float), cudaMemcpyDeviceToDevice);

    for (int l = 0; l < DEPTH; l++) {
        const size_t woffQ = (size_t)l * DIMN * 3 * DIMN;
        const size_t woffO = (size_t)l * DIMN * DIMN;
        const size_t woff1 = (size_t)l * DIMN * MLPD;
        const size_t woff2 = (size_t)l * MLPD * DIMN;
        const float* bo  = bout + (size_t)l * DIMN;
        const float* g1  = ln1g + (size_t)l * DIMN;
        const float* bb1 = ln1b + (size_t)l * DIMN;
        const float* g2  = ln2g + (size_t)l * DIMN;
        const float* bb2 = ln2b + (size_t)l * DIMN;
        const float* bf1 = b1   + (size_t)l * MLPD;
        const float* bf2 = b2   + (size_t)l * DIMN;

        ln_pack_h<<<TOK, 256>>>(h, g1, bb1, y16);
        gemm_mma<1,1><<<dim3(3 * DIMN / 128, TOK / 128), 256, GEMM_SMEM>>>(
            TOK, 3 * DIMN, DIMN, y16, nullptr, wq16 + woffQ, nullptr,
            nullptr, nullptr, qp16, nullptr, 3 * DIMN / 64, 0, FLAG_PACK);
        attn_mma<<<dim3(SEQ / 64, BATCH * HEADS), 128, ATT_SMEM>>>(qp16, at16);
        gemm_mma<1,1><<<dim3(DIMN / 128, TOK / 128), 256, GEMM_SMEM>>>(
            TOK, DIMN, DIMN, at16, nullptr, wo16 + woffO, nullptr,
            h, bo, nullptr, nullptr, 0, 0, FLAG_RESID);
        ln_pack_bf<<<TOK, 256>>>(h, g2, bb2, yh, yl);
        gemm_mma<3,0><<<dim3(MLPD / 128, TOK / 128), 256, GEMM_SMEM>>>(
            TOK, MLPD, DIMN, yh, yl, w1h + woff1, w1l + woff1,
            nullptr, bf1, uh, ul, MLPD / 64, MLPD, FLAG_GELU | FLAG_PACK);
        gemm_mma<3,0><<<dim3(DIMN / 128, TOK / 128), 256, GEMM_SMEM>>>(
            TOK, DIMN, MLPD, uh, ul, w2h + woff2, w2l + woff2,
            h, bf2, nullptr, nullptr, 0, 0, FLAG_RESID);
    }
}